// round 11
// baseline (speedup 1.0000x reference)
#include <cuda_runtime.h>

// Detection1D: B=64, N=131072, C=1. Decode + per-batch greedy NMS (TOP_K=10).
// ONE kernel, TWO CTAs per batch (128 CTAs = one wave, co-resident).
//   Partner CTA (odd): filters its half-batch (score > 0.999) into smem,
//     dumps keys to g_part, release fence, sets flag, exits.
//   Owner CTA (even): filters its half, spin-waits partner flag (symmetric
//     work -> near-zero wait), merges keys, decodes boxes, then warp 0 runs
//     the 10 exact argmax+suppress rounds (jnp.argmax tie-break via
//     (score_bits<<32)|~idx keys). Overflow/exhaustion -> exact full-N
//     fallback (block-uniform). Owner resets the flag (replay-safe; flags
//     are static zero-init).
// Threshold 0.999: 10th order statistic of 131072 uniforms ~0.99992 ->
// candidates are a provable superset of any greedy selection unless the
// shortlist exhausts, which the fallback covers exactly.

#define NB 64
#define NN 131072            // 2^17
#define HALF (NN / 2)        // 65536 elements per CTA
#define HALF4 (HALF / 4)     // 16384 float4 per CTA
#define NT 1024
#define UF 8                 // front-batched float4 loads per thread per iter
#define CAPH 512             // per-half candidate cap (E~65, huge margin)
#define MCAP (2 * CAPH)
#define TOPK 10
#define THRESH 0.999f

__device__ unsigned long long g_part[NB * CAPH];  // partner key dump
__device__ int g_flag[NB];                        // 0 = not ready; cnt+1 = ready

__global__ void __launch_bounds__(NT) k_all(
    const float4* __restrict__ clf4,
    const float*  __restrict__ clf,
    const float2* __restrict__ reg,
    const float2* __restrict__ prop,
    float*        __restrict__ out)
{
    const int b    = blockIdx.x >> 1;
    const int half = blockIdx.x & 1;
    const int tid  = threadIdx.x;

    __shared__ unsigned long long skey[MCAP];
    __shared__ float sx1[MCAP], sx2[MCAP];
    __shared__ float selX1[TOPK], selX2[TOPK], selSc[TOPK];
    __shared__ unsigned selIdx[TOPK];
    __shared__ int s_cnt, s_nsel, s_mode, s_part;

    if (tid == 0) { s_cnt = 0; s_nsel = 0; s_mode = 0; }
    __syncthreads();

    // ---------------- phase 1: filter my half into SMEM ---------------------
    {
        const float4* c4 = clf4 + (size_t)b * (NN / 4) + (size_t)half * HALF4;
        const unsigned eoff = (unsigned)half * HALF;
        for (int base = 0; base < HALF4; base += NT * UF) {   // 2 iters
            float4 v[UF];
#pragma unroll
            for (int u = 0; u < UF; u++)       // front-batched coalesced loads
                v[u] = c4[base + u * NT + tid];
#pragma unroll
            for (int u = 0; u < UF; u++) {
                float mx = fmaxf(fmaxf(v[u].x, v[u].y), fmaxf(v[u].z, v[u].w));
                if (mx > THRESH) {             // rare (~1.6% of float4s)
                    float ss[4] = { v[u].x, v[u].y, v[u].z, v[u].w };
                    const unsigned e0 = eoff + (unsigned)((base + u * NT + tid) * 4);
#pragma unroll
                    for (int j = 0; j < 4; j++) {
                        if (ss[j] > THRESH) {
                            int pos = atomicAdd(&s_cnt, 1);
                            if (pos < CAPH)
                                skey[pos] =
                                    ((unsigned long long)__float_as_uint(ss[j]) << 32)
                                  | (unsigned long long)(0xFFFFFFFFu - (e0 + j));
                        }
                    }
                }
            }
        }
    }
    __syncthreads();
    const int own_cnt = s_cnt;

    // ---------------- partner: dump keys, flag, exit ------------------------
    if (half == 1) {
        const int w = min(own_cnt, CAPH);
        for (int i = tid; i < w; i += NT)
            g_part[b * CAPH + i] = skey[i];
        __threadfence();
        __syncthreads();
        if (tid == 0)
            atomicExch(&g_flag[b], own_cnt + 1);   // nonzero ready token
        return;                                    // block-uniform
    }

    // ---------------- owner: wait partner, merge ----------------------------
    if (tid == 0) {
        int v;
        while ((v = atomicAdd(&g_flag[b], 0)) == 0) { }
        __threadfence();                           // acquire
        s_part = v - 1;
    }
    __syncthreads();
    const int part_cnt = s_part;
    const int own_m    = min(own_cnt, CAPH);
    const int part_m   = min(part_cnt, CAPH);
    const int m        = own_m + part_m;
    if (tid == 0 && (own_cnt > CAPH || part_cnt > CAPH)) s_mode = 1;

    for (int i = tid; i < part_m; i += NT)
        skey[own_m + i] = g_part[b * CAPH + i];
    __syncthreads();

    const float2* regb  = reg  + (size_t)b * NN;
    const float2* propb = prop + (size_t)b * NN;

    // ---------------- phase 2: decode merged shortlist ----------------------
    for (int i = tid; i < m; i += NT) {
        unsigned long long key = skey[i];
        unsigned idx = 0xFFFFFFFFu - (unsigned)(key & 0xFFFFFFFFu);
        float2 r = regb[idx];
        float2 p = propb[idx];
        float w   = p.y - p.x;
        float ctr = p.x + 0.5f * w;
        float pc  = ctr + (r.x * 0.1f) * w;
        float pw  = expf(r.y * 0.2f) * w;
        float x1 = fminf(fmaxf(pc - 0.5f * pw, 0.0f), 416.0f);
        float x2 = fminf(fmaxf(pc + 0.5f * pw, 0.0f), 416.0f);
        if (!(x2 - x1 > 3.0f)) skey[i] = 0ULL;     // fails length test
        sx1[i] = x1;
        sx2[i] = x2;
    }
    __syncthreads();

    // ---------------- phase 3: warp 0, 10 argmax+suppress rounds ------------
    if (tid < 32 && s_mode == 0) {
        const int lane = tid;
        int nsel = 0;
        for (int t = 0; t < TOPK; t++) {
            unsigned long long bestk = 0ULL;
            float bx1 = 0.f, bx2 = 0.f;
            for (int i = lane; i < m; i += 32) {
                unsigned long long k = skey[i];
                if (k > bestk) { bestk = k; bx1 = sx1[i]; bx2 = sx2[i]; }
            }
            // xor-reduce the key, then fetch winner's box via ballot
            unsigned long long red = bestk;
#pragma unroll
            for (int o = 16; o > 0; o >>= 1) {
                unsigned long long k2 = __shfl_xor_sync(0xFFFFFFFFu, red, o);
                if (k2 > red) red = k2;
            }
            if (red == 0ULL) break;                // exhausted (warp-uniform)
            unsigned win = __ballot_sync(0xFFFFFFFFu, bestk == red);
            int wl = __ffs(win) - 1;               // keys unique -> one winner
            bx1 = __shfl_sync(0xFFFFFFFFu, bx1, wl);
            bx2 = __shfl_sync(0xFFFFFFFFu, bx2, wl);

            unsigned bidx = 0xFFFFFFFFu - (unsigned)(red & 0xFFFFFFFFu);
            if (lane == 0) {
                selSc[t]  = __uint_as_float((unsigned)(red >> 32));
                selIdx[t] = bidx;
                selX1[t]  = bx1;
                selX2[t]  = bx2;
            }
            nsel = t + 1;

            float blen = bx2 - bx1;
            for (int i = lane; i < m; i += 32) {
                unsigned long long k = skey[i];
                if (k == 0ULL) continue;
                float x1 = sx1[i], x2 = sx2[i];
                float inter = fmaxf(fminf(x2, bx2) - fmaxf(x1, bx1), 0.0f);
                float uni   = (x2 - x1) + blen - inter + 1e-9f;
                unsigned idx = 0xFFFFFFFFu - (unsigned)(k & 0xFFFFFFFFu);
                if (inter / uni > 0.5f || idx == bidx) skey[i] = 0ULL;
            }
            __syncwarp();
        }
        if (lane == 0) {
            s_nsel = nsel;
            if (nsel < TOPK) s_mode = 1;           // exhausted -> full-N fallback
        }
    }
    __syncthreads();

    // ---------------- fallback: exact full-N scans (rarely/never runs) ------
    if (s_mode == 1) {
        __shared__ unsigned long long r_key[NT / 32];
        __shared__ float r_x1[NT / 32], r_x2[NT / 32];
        const float* clfb = clf + (size_t)b * NN;
        for (int t = s_nsel; t < TOPK; t++) {
            unsigned long long best = 0ULL;
            float bx1 = 0.f, bx2 = 0.f;
            for (int i = tid; i < NN; i += NT) {
                float s = clfb[i];
                if (s <= 0.01f) continue;
                float2 r = regb[i];
                float2 p = propb[i];
                float w   = p.y - p.x;
                float ctr = p.x + 0.5f * w;
                float pc  = ctr + (r.x * 0.1f) * w;
                float pw  = expf(r.y * 0.2f) * w;
                float x1 = fminf(fmaxf(pc - 0.5f * pw, 0.0f), 416.0f);
                float x2 = fminf(fmaxf(pc + 0.5f * pw, 0.0f), 416.0f);
                float len = x2 - x1;
                if (len <= 3.0f) continue;
                bool sup = false;
                for (int j = 0; j < t; j++) {
                    if ((unsigned)i == selIdx[j]) { sup = true; break; }
                    float inter = fmaxf(fminf(x2, selX2[j]) - fmaxf(x1, selX1[j]), 0.0f);
                    float uni   = len + (selX2[j] - selX1[j]) - inter + 1e-9f;
                    if (inter / uni > 0.5f) { sup = true; break; }
                }
                if (sup) continue;
                unsigned long long k =
                    ((unsigned long long)__float_as_uint(s) << 32)
                  | (unsigned long long)(0xFFFFFFFFu - (unsigned)i);
                if (k > best) { best = k; bx1 = x1; bx2 = x2; }
            }
#pragma unroll
            for (int o = 16; o > 0; o >>= 1) {
                unsigned long long k2 = __shfl_down_sync(0xFFFFFFFFu, best, o);
                float a2 = __shfl_down_sync(0xFFFFFFFFu, bx1, o);
                float b2 = __shfl_down_sync(0xFFFFFFFFu, bx2, o);
                if (k2 > best) { best = k2; bx1 = a2; bx2 = b2; }
            }
            if ((tid & 31) == 0) {
                int w = tid >> 5;
                r_key[w] = best; r_x1[w] = bx1; r_x2[w] = bx2;
            }
            __syncthreads();
            if (tid == 0) {
                best = 0ULL;
                for (int w = 0; w < NT / 32; w++)
                    if (r_key[w] > best) { best = r_key[w]; bx1 = r_x1[w]; bx2 = r_x2[w]; }
                if (best == 0ULL) {
                    s_mode = 2;   // nothing left -> -1 rows from here on
                } else {
                    selSc[t]  = __uint_as_float((unsigned)(best >> 32));
                    selIdx[t] = 0xFFFFFFFFu - (unsigned)(best & 0xFFFFFFFFu);
                    selX1[t]  = bx1;
                    selX2[t]  = bx2;
                    s_nsel = t + 1;
                }
            }
            __syncthreads();
            if (s_mode == 2) break;
        }
    }

    __syncthreads();
    if (tid < TOPK) {
        int t = tid;
        float a = -1.0f, c = -1.0f, s = -1.0f;
        if (t < s_nsel) { a = selX1[t]; c = selX2[t]; s = selSc[t]; }
        out[b * (TOPK * 3) + t * 3 + 0] = a;
        out[b * (TOPK * 3) + t * 3 + 1] = c;
        out[b * (TOPK * 3) + t * 3 + 2] = s;
    }
    if (tid == 0) g_flag[b] = 0;   // replay-clean (static zero-init otherwise)
}

extern "C" void kernel_launch(void* const* d_in, const int* in_sizes, int n_in,
                              void* d_out, int out_size)
{
    const float*  clf  = (const float*)d_in[0];                 // (64,131072,1)
    const float2* reg  = (const float2*)d_in[1];                // (64,131072,2)
    const float2* prop = (const float2*)d_in[2];                // (64,131072,2)
    float* out = (float*)d_out;                                 // (64,10,3)

    k_all<<<NB * 2, NT>>>((const float4*)clf, clf, reg, prop, out);
}

// round 12
// speedup vs baseline: 1.6520x; 1.6520x over previous
#include <cuda_runtime.h>

// Detection1D: B=64, N=131072, C=1. Decode + per-batch greedy NMS (TOP_K=10).
// ONE kernel, ONE block per batch. Tail restructured for minimum serial latency:
//   Phase 1: stream clf (front-batched float4 loads). Hits (score>0.999;
//     provable superset of any greedy selection unless the shortlist
//     exhausts) are decoded INLINE (reg/prop gather overlaps streaming) and
//     pushed (key,x1,x2) into SMEM; length<=3 dropped at source.
//   Phase 2a: rank-sort the ~131 candidates (thread-per-candidate count of
//     greater keys; keys unique -> exact descending order = argmax order
//     with jnp first-index tie-break via (score<<32)|~idx packing).
//   Phase 2b: all 1024 threads build the pairwise IoU>0.5 suppression bit
//     matrix in one parallel sweep.
//   Phase 2c: thread 0 walks sorted order once: pick first unsuppressed,
//     OR in its mask row. Provably identical to greedy argmax+suppress.
//   Overflow/exhaustion -> exact full-N fallback (block-uniform).

#define NB 64
#define NN 131072            // 2^17
#define NN4 (NN / 4)
#define NT 1024
#define UF 8
#define CAP 256              // E[m]~131, sigma~11 -> 11-sigma margin
#define MW 8                 // mask words per row (256/32)
#define TOPK 10
#define THRESH 0.999f

__global__ void __launch_bounds__(NT) k_all(
    const float4* __restrict__ clf4,
    const float*  __restrict__ clf,
    const float2* __restrict__ reg,
    const float2* __restrict__ prop,
    float*        __restrict__ out)
{
    const int b   = blockIdx.x;
    const int tid = threadIdx.x;

    __shared__ unsigned long long skey[CAP], skey2[CAP];
    __shared__ float sx1[CAP], sx2[CAP], sy1[CAP], sy2[CAP];
    __shared__ unsigned smask[CAP * MW];            // 8 KB suppression matrix
    __shared__ float selX1[TOPK], selX2[TOPK], selSc[TOPK];
    __shared__ unsigned selIdx[TOPK];
    __shared__ int s_cnt, s_nsel, s_mode;

    if (tid == 0) { s_cnt = 0; s_nsel = 0; s_mode = 0; }
#pragma unroll
    for (int w = tid; w < CAP * MW; w += NT) smask[w] = 0;
    __syncthreads();

    const float2* regb  = reg  + (size_t)b * NN;
    const float2* propb = prop + (size_t)b * NN;

    // ---------- phase 1: stream + inline decode into SMEM -------------------
    {
        const float4* c4 = clf4 + (size_t)b * NN4;
        for (int base = 0; base < NN4; base += NT * UF) {       // 4 iters
            float4 v[UF];
#pragma unroll
            for (int u = 0; u < UF; u++)
                v[u] = c4[base + u * NT + tid];
#pragma unroll
            for (int u = 0; u < UF; u++) {
                float mx = fmaxf(fmaxf(v[u].x, v[u].y), fmaxf(v[u].z, v[u].w));
                if (mx > THRESH) {                  // ~1.6% of float4s
                    float ss[4] = { v[u].x, v[u].y, v[u].z, v[u].w };
                    const unsigned e0 = (unsigned)((base + u * NT + tid) * 4);
#pragma unroll
                    for (int j = 0; j < 4; j++) {
                        if (ss[j] > THRESH) {
                            unsigned idx = e0 + j;
                            float2 r = regb[idx];
                            float2 p = propb[idx];
                            float w   = p.y - p.x;
                            float ctr = p.x + 0.5f * w;
                            float pc  = ctr + (r.x * 0.1f) * w;
                            float pw  = expf(r.y * 0.2f) * w;
                            float x1 = fminf(fmaxf(pc - 0.5f * pw, 0.0f), 416.0f);
                            float x2 = fminf(fmaxf(pc + 0.5f * pw, 0.0f), 416.0f);
                            if (x2 - x1 > 3.0f) {   // inert otherwise: drop
                                int pos = atomicAdd(&s_cnt, 1);
                                if (pos < CAP) {
                                    skey[pos] =
                                        ((unsigned long long)__float_as_uint(ss[j]) << 32)
                                      | (unsigned long long)(0xFFFFFFFFu - idx);
                                    sx1[pos] = x1;
                                    sx2[pos] = x2;
                                }
                            }
                        }
                    }
                }
            }
        }
    }
    __syncthreads();

    const int  cnt  = s_cnt;
    const int  m    = min(cnt, CAP);
    const bool fast = (cnt <= CAP);                 // block-uniform

    // ---------- phase 2a: rank-sort (descending, unique keys) ---------------
    if (fast && tid < m) {
        unsigned long long myk = skey[tid];
        int rank = 0;
        for (int j = 0; j < m; j++)                 // broadcast smem reads
            rank += (skey[j] > myk);
        skey2[rank] = myk;
        sy1[rank]   = sx1[tid];
        sy2[rank]   = sx2[tid];
    }
    __syncthreads();

    // ---------- phase 2b: pairwise suppression matrix -----------------------
    if (fast) {
        const int mm = m * m;
        for (int p = tid; p < mm; p += NT) {
            int i = p / m;
            int j = p - i * m;
            if (i < j) {
                float a1 = sy1[i], a2 = sy2[i];
                float b1 = sy1[j], b2 = sy2[j];
                float inter = fmaxf(fminf(a2, b2) - fmaxf(a1, b1), 0.0f);
                float uni   = (a2 - a1) + (b2 - b1) - inter + 1e-9f;
                if (inter > 0.5f * uni)             // iou > 0.5
                    atomicOr(&smask[i * MW + (j >> 5)], 1u << (j & 31));
            }
        }
    }
    __syncthreads();

    // ---------- phase 2c: single greedy walk (thread 0) ---------------------
    if (tid == 0) {
        if (fast) {
            unsigned sup[MW] = {0, 0, 0, 0, 0, 0, 0, 0};
            int ns = 0;
            for (int i = 0; i < m && ns < TOPK; i++) {
                if (!((sup[i >> 5] >> (i & 31)) & 1u)) {
                    unsigned long long k = skey2[i];
                    selSc[ns]  = __uint_as_float((unsigned)(k >> 32));
                    selIdx[ns] = 0xFFFFFFFFu - (unsigned)(k & 0xFFFFFFFFu);
                    selX1[ns]  = sy1[i];
                    selX2[ns]  = sy2[i];
                    ns++;
#pragma unroll
                    for (int w = 0; w < MW; w++)
                        sup[w] |= smask[i * MW + w];
                }
            }
            s_nsel = ns;
            if (ns < TOPK) s_mode = 1;              // exhausted -> full-N
        } else {
            s_mode = 1;                             // overflow -> full-N
        }
    }
    __syncthreads();

    // ---------- fallback: exact full-N scans (rarely/never runs) ------------
    if (s_mode == 1) {
        __shared__ unsigned long long r_key[NT / 32];
        __shared__ float r_x1[NT / 32], r_x2[NT / 32];
        const float* clfb = clf + (size_t)b * NN;
        for (int t = s_nsel; t < TOPK; t++) {
            unsigned long long best = 0ULL;
            float bx1 = 0.f, bx2 = 0.f;
            for (int i = tid; i < NN; i += NT) {
                float s = clfb[i];
                if (s <= 0.01f) continue;
                float2 r = regb[i];
                float2 p = propb[i];
                float w   = p.y - p.x;
                float ctr = p.x + 0.5f * w;
                float pc  = ctr + (r.x * 0.1f) * w;
                float pw  = expf(r.y * 0.2f) * w;
                float x1 = fminf(fmaxf(pc - 0.5f * pw, 0.0f), 416.0f);
                float x2 = fminf(fmaxf(pc + 0.5f * pw, 0.0f), 416.0f);
                float len = x2 - x1;
                if (len <= 3.0f) continue;
                bool sup = false;
                for (int j = 0; j < t; j++) {
                    if ((unsigned)i == selIdx[j]) { sup = true; break; }
                    float inter = fmaxf(fminf(x2, selX2[j]) - fmaxf(x1, selX1[j]), 0.0f);
                    float uni   = len + (selX2[j] - selX1[j]) - inter + 1e-9f;
                    if (inter / uni > 0.5f) { sup = true; break; }
                }
                if (sup) continue;
                unsigned long long k =
                    ((unsigned long long)__float_as_uint(s) << 32)
                  | (unsigned long long)(0xFFFFFFFFu - (unsigned)i);
                if (k > best) { best = k; bx1 = x1; bx2 = x2; }
            }
#pragma unroll
            for (int o = 16; o > 0; o >>= 1) {
                unsigned long long k2 = __shfl_down_sync(0xFFFFFFFFu, best, o);
                float a2 = __shfl_down_sync(0xFFFFFFFFu, bx1, o);
                float b2 = __shfl_down_sync(0xFFFFFFFFu, bx2, o);
                if (k2 > best) { best = k2; bx1 = a2; bx2 = b2; }
            }
            if ((tid & 31) == 0) {
                int w = tid >> 5;
                r_key[w] = best; r_x1[w] = bx1; r_x2[w] = bx2;
            }
            __syncthreads();
            if (tid == 0) {
                best = 0ULL;
                for (int w = 0; w < NT / 32; w++)
                    if (r_key[w] > best) { best = r_key[w]; bx1 = r_x1[w]; bx2 = r_x2[w]; }
                if (best == 0ULL) {
                    s_mode = 2;   // nothing left -> -1 rows from here on
                } else {
                    selSc[t]  = __uint_as_float((unsigned)(best >> 32));
                    selIdx[t] = 0xFFFFFFFFu - (unsigned)(best & 0xFFFFFFFFu);
                    selX1[t]  = bx1;
                    selX2[t]  = bx2;
                    s_nsel = t + 1;
                }
            }
            __syncthreads();
            if (s_mode == 2) break;
        }
    }

    __syncthreads();
    if (tid < TOPK) {
        int t = tid;
        float a = -1.0f, c = -1.0f, s = -1.0f;
        if (t < s_nsel) { a = selX1[t]; c = selX2[t]; s = selSc[t]; }
        out[b * (TOPK * 3) + t * 3 + 0] = a;
        out[b * (TOPK * 3) + t * 3 + 1] = c;
        out[b * (TOPK * 3) + t * 3 + 2] = s;
    }
}

extern "C" void kernel_launch(void* const* d_in, const int* in_sizes, int n_in,
                              void* d_out, int out_size)
{
    const float*  clf  = (const float*)d_in[0];                 // (64,131072,1)
    const float2* reg  = (const float2*)d_in[1];                // (64,131072,2)
    const float2* prop = (const float2*)d_in[2];                // (64,131072,2)
    float* out = (float*)d_out;                                 // (64,10,3)

    k_all<<<NB, NT>>>((const float4*)clf, clf, reg, prop, out);
}